// round 2
// baseline (speedup 1.0000x reference)
#include <cuda_runtime.h>

// IF (integrate-and-fire) scan, persistent single-wave version.
//   x: (B=32, T=8, CHW=200704) fp32. Per neuron: 8-step serial scan.
// Pure streaming (205.5MB in + 205.5MB out). R1 showed DRAM=78.1%,
// ~8 CTA waves -> ~16K cycles of wave-transition overhead. This round:
// one persistent wave (888 CTAs = 148 SMs x 6 resident), grid-stride,
// streaming load/store hints to keep L2 evict-first.

#define T_STEPS 8
#define BATCH 32
#define CHW4 50176              // (64*56*56)/4 float4 per timestep-slice
#define VTH 1.0f

__global__ void __launch_bounds__(256) if_scan_kernel(
    const float4* __restrict__ x, float4* __restrict__ out)
{
    const int total = BATCH * CHW4;               // 1,605,632
    const int stride = gridDim.x * blockDim.x;    // 888*256 = 227,328

    for (int idx = blockIdx.x * blockDim.x + threadIdx.x;
         idx < total; idx += stride)
    {
        const int b = idx / CHW4;                 // magic-mul, cheap
        const int p = idx - b * CHW4;
        const float4* xp = x   + (long long)b * T_STEPS * CHW4 + p;
        float4*       op = out + (long long)b * T_STEPS * CHW4 + p;

        // Front-batch all 8 loads (independent of scan state) -> MLP=8
        float4 xt[T_STEPS];
#pragma unroll
        for (int t = 0; t < T_STEPS; t++)
            xt[t] = __ldcs(xp + t * CHW4);

        float mx = 0.f, my = 0.f, mz = 0.f, mw = 0.f;
#pragma unroll
        for (int t = 0; t < T_STEPS; t++) {
            mx += xt[t].x; my += xt[t].y; mz += xt[t].z; mw += xt[t].w;
            float4 s;
            s.x = (mx > VTH) ? 1.0f : 0.0f;
            s.y = (my > VTH) ? 1.0f : 0.0f;
            s.z = (mz > VTH) ? 1.0f : 0.0f;
            s.w = (mw > VTH) ? 1.0f : 0.0f;
            mx = (mx > VTH) ? 0.0f : mx;
            my = (my > VTH) ? 0.0f : my;
            mz = (mz > VTH) ? 0.0f : mz;
            mw = (mw > VTH) ? 0.0f : mw;
            __stcs(op + t * CHW4, s);
        }
    }
}

extern "C" void kernel_launch(void* const* d_in, const int* in_sizes, int n_in,
                              void* d_out, int out_size)
{
    const float4* x = (const float4*)d_in[0];
    float4* out = (float4*)d_out;
    // One full wave: 148 SMs x 6 resident CTAs (40 regs/thread, 256 thr/CTA)
    const int blocks = 148 * 6;
    if_scan_kernel<<<blocks, 256>>>(x, out);
}

// round 3
// speedup vs baseline: 1.0920x; 1.0920x over previous
#include <cuda_runtime.h>

// IF (integrate-and-fire) scan — R1 structure (best: 57.6us kernel, DRAM 78%)
// with evict-first streaming stores. x: (B=32, T=8, CHW=200704) fp32.
// One thread owns one float4 across all 8 timesteps; 8 front-batched loads
// (MLP=8), 8 streaming stores. Pure HBM stream: 205.5MB in + 205.5MB out.
// R2 lesson: persistent grid-stride regressed (-12%); exact grid is better.

#define T_STEPS 8
#define BATCH 32
#define CHW4 50176              // (64*56*56)/4 float4 per timestep-slice
#define VTH 1.0f

__global__ void __launch_bounds__(256) if_scan_kernel(
    const float4* __restrict__ x, float4* __restrict__ out)
{
    const long long idx = (long long)blockIdx.x * blockDim.x + threadIdx.x;
    const long long total = (long long)BATCH * CHW4;   // 1,605,632
    if (idx >= total) return;

    const int b = (int)(idx / CHW4);
    const int p = (int)(idx % CHW4);
    const long long base = (long long)b * T_STEPS * CHW4 + p;

    // Front-batch all 8 loads (independent of scan state) -> MLP=8
    float4 xt[T_STEPS];
#pragma unroll
    for (int t = 0; t < T_STEPS; t++)
        xt[t] = x[base + (long long)t * CHW4];

    float mx = 0.f, my = 0.f, mz = 0.f, mw = 0.f;
#pragma unroll
    for (int t = 0; t < T_STEPS; t++) {
        mx += xt[t].x; my += xt[t].y; mz += xt[t].z; mw += xt[t].w;
        float4 s;
        s.x = (mx > VTH) ? 1.0f : 0.0f;
        s.y = (my > VTH) ? 1.0f : 0.0f;
        s.z = (mz > VTH) ? 1.0f : 0.0f;
        s.w = (mw > VTH) ? 1.0f : 0.0f;
        mx = (mx > VTH) ? 0.0f : mx;
        my = (my > VTH) ? 0.0f : my;
        mz = (mz > VTH) ? 0.0f : mz;
        mw = (mw > VTH) ? 0.0f : mw;
        // Evict-first store: output is never re-read; keep L2 for the read stream.
        __stcs(out + base + (long long)t * CHW4, s);
    }
}

extern "C" void kernel_launch(void* const* d_in, const int* in_sizes, int n_in,
                              void* d_out, int out_size)
{
    const float4* x = (const float4*)d_in[0];
    float4* out = (float4*)d_out;
    const long long total = (long long)BATCH * CHW4;
    const int threads = 256;
    const int blocks = (int)((total + threads - 1) / threads);
    if_scan_kernel<<<blocks, threads>>>(x, out);
}